// round 4
// baseline (speedup 1.0000x reference)
#include <cuda_runtime.h>
#include <cuda_bf16.h>
#include <math.h>

#define MAX_NODES 50000
#define D 16

// Scratch (allocation-free rule: __device__ globals)
__device__ int   g_deg[MAX_NODES];
__device__ float g_xT[MAX_NODES * D];   // node-major normalized reps [n][16]
__device__ float g_comp[MAX_NODES * D]; // comparison accumulator [n][16]

// Vectorized global reduction (CUTLASS-validated syntax, PTX ISA 8.1+, sm_90+)
__device__ __forceinline__ void red_add_v4(float* addr, float a, float b, float c, float d) {
    asm volatile("red.global.add.v4.f32 [%0], {%1, %2, %3, %4};"
                 :: "l"(addr), "f"(a), "f"(b), "f"(c), "f"(d)
                 : "memory");
}

// ---------------------------------------------------------------- K0: zero scratch + out
__global__ void k_zero(int n_nodes, float* out) {
    int i = blockIdx.x * blockDim.x + threadIdx.x;
    int total = n_nodes * D;
    if (i < total) g_comp[i] = 0.0f;
    if (i < n_nodes) g_deg[i] = 0;
    if (i == 0) out[0] = 0.0f;
}

// ---------------------------------------------------------------- K1: in-degree on dst
__global__ void k_degree(const int* __restrict__ dst, int n_edges, int n_nodes) {
    int e = blockIdx.x * blockDim.x + threadIdx.x;
    if (e < n_edges) {
        int d = dst[e];
        if (d >= 0 && d < n_nodes) atomicAdd(&g_deg[d], 1);
    }
}

// ---------------------------------------------------------------- K2: normalize + transpose
// entity_reps is [D, n_nodes] row-major; tid = i*n_nodes + n gives coalesced reads.
__global__ void k_norm(const float* __restrict__ reps, int n_nodes) {
    int tid = blockIdx.x * blockDim.x + threadIdx.x;
    int total = D * n_nodes;
    if (tid >= total) return;
    int i = tid / n_nodes;
    int n = tid - i * n_nodes;
    int deg = g_deg[n];
    float inv = (deg > 0) ? rsqrtf((float)deg) : 0.0f;
    g_xT[n * D + i] = reps[tid] * inv;
}

// ---------------------------------------------------------------- K3: per-edge matvecs + scatter
__device__ __forceinline__ void matvec_scatter(const float4* __restrict__ M,
                                               const float4* __restrict__ xv,
                                               float* cbase, float sign) {
    float4 a0 = xv[0], a1 = xv[1], a2 = xv[2], a3 = xv[3];
    #pragma unroll
    for (int g = 0; g < 4; g++) {
        float o[4];
        #pragma unroll
        for (int r = 0; r < 4; r++) {
            int row = g * 4 + r;
            float4 r0 = M[row * 4 + 0];
            float4 r1 = M[row * 4 + 1];
            float4 r2 = M[row * 4 + 2];
            float4 r3 = M[row * 4 + 3];
            o[r] = r0.x*a0.x + r0.y*a0.y + r0.z*a0.z + r0.w*a0.w
                 + r1.x*a1.x + r1.y*a1.y + r1.z*a1.z + r1.w*a1.w
                 + r2.x*a2.x + r2.y*a2.y + r2.z*a2.z + r2.w*a2.w
                 + r3.x*a3.x + r3.y*a3.y + r3.z*a3.z + r3.w*a3.w;
        }
        red_add_v4(cbase + g * 4, sign*o[0], sign*o[1], sign*o[2], sign*o[3]);
    }
}

__global__ void __launch_bounds__(256)
k_edge(const float* __restrict__ R,     // [16,16,16,16]
       const int*   __restrict__ src,
       const int*   __restrict__ dst,
       const int*   __restrict__ types,
       int n_edges) {
    int e = blockIdx.x * blockDim.x + threadIdx.x;
    if (e >= n_edges) return;

    int s = src[e];
    int d = dst[e];
    int ts = types[s];
    int td = types[d];

    // head: R[ts][td] @ x[s]  -> +comp[s]
    matvec_scatter(reinterpret_cast<const float4*>(R + (((ts << 4) + td) << 8)),
                   reinterpret_cast<const float4*>(g_xT + s * D),
                   g_comp + s * D, 1.0f);
    // tail: R[td][ts] @ x[d]  -> -comp[d]
    matvec_scatter(reinterpret_cast<const float4*>(R + (((td << 4) + ts) << 8)),
                   reinterpret_cast<const float4*>(g_xT + d * D),
                   g_comp + d * D, -1.0f);
}

// ---------------------------------------------------------------- K4: sum of squares
__global__ void k_sumsq(int n_nodes, float* out) {
    int total4 = (n_nodes * D) / 4;   // D=16 -> divisible by 4
    const float4* c4 = reinterpret_cast<const float4*>(g_comp);
    float acc = 0.0f;
    for (int i = blockIdx.x * blockDim.x + threadIdx.x; i < total4;
         i += gridDim.x * blockDim.x) {
        float4 v = c4[i];
        acc += v.x*v.x + v.y*v.y + v.z*v.z + v.w*v.w;
    }
    #pragma unroll
    for (int off = 16; off > 0; off >>= 1)
        acc += __shfl_down_sync(0xFFFFFFFFu, acc, off);
    __shared__ float warp_sums[32];
    int lane = threadIdx.x & 31;
    int wid  = threadIdx.x >> 5;
    if (lane == 0) warp_sums[wid] = acc;
    __syncthreads();
    if (wid == 0) {
        int nwarps = (blockDim.x + 31) >> 5;
        float v = (lane < nwarps) ? warp_sums[lane] : 0.0f;
        #pragma unroll
        for (int off = 16; off > 0; off >>= 1)
            v += __shfl_down_sync(0xFFFFFFFFu, v, off);
        if (lane == 0) atomicAdd(out, v);
    }
}

// ---------------------------------------------------------------- launch
extern "C" void kernel_launch(void* const* d_in, const int* in_sizes, int n_in,
                              void* d_out, int out_size) {
    const float* reps  = (const float*)d_in[0];  // [16, n_nodes]
    const float* rmaps = (const float*)d_in[1];  // [16,16,16,16]
    const int*   eidx  = (const int*)d_in[2];    // [2, n_edges]
    const int*   types = (const int*)d_in[3];    // [n_nodes]
    float* out = (float*)d_out;

    int n_nodes = in_sizes[3];
    if (n_nodes > MAX_NODES) n_nodes = MAX_NODES;   // defensive: scratch bound
    int n_edges = in_sizes[2] / 2;
    const int* src = eidx;
    const int* dst = eidx + n_edges;

    const int T = 256;
    int total_nd = n_nodes * D;

    k_zero  <<<(total_nd + T - 1) / T, T>>>(n_nodes, out);
    k_degree<<<(n_edges + T - 1) / T, T>>>(dst, n_edges, n_nodes);
    k_norm  <<<(total_nd + T - 1) / T, T>>>(reps, n_nodes);
    k_edge  <<<(n_edges + T - 1) / T, T>>>(rmaps, src, dst, types, n_edges);
    k_sumsq <<<296, 256>>>(n_nodes, out);
}

// round 5
// speedup vs baseline: 4.1360x; 4.1360x over previous
#include <cuda_runtime.h>
#include <cuda_bf16.h>
#include <math.h>

#define MAX_NODES 50000
#define D 16
#define NTYPES 16

// Scratch (allocation-free rule: __device__ globals)
__device__ int   g_cnt[MAX_NODES * NTYPES]; // signed type counts per node
__device__ int   g_deg[MAX_NODES];          // in-degree (on dst)
__device__ float g_xT[MAX_NODES * D];       // node-major normalized reps [n][16]

// ---------------------------------------------------------------- K0: zero scratch + out
__global__ void k_zero(int n_nodes, float* out) {
    int i = blockIdx.x * blockDim.x + threadIdx.x;
    int total = n_nodes * NTYPES;
    if (i < total) g_cnt[i] = 0;
    if (i < n_nodes) g_deg[i] = 0;
    if (i == 0) out[0] = 0.0f;
}

// ---------------------------------------------------------------- K1: per-edge type counts + degree
// head at src uses R[ts][td]  -> cnt[s][td] += 1
// tail at dst uses R[td][ts]  -> cnt[d][ts] -= 1
__global__ void __launch_bounds__(256)
k_count(const int* __restrict__ src, const int* __restrict__ dst,
        const int* __restrict__ types, int n_edges) {
    int e = blockIdx.x * blockDim.x + threadIdx.x;
    if (e >= n_edges) return;
    int s  = src[e];
    int d  = dst[e];
    int ts = __ldg(types + s);
    int td = __ldg(types + d);
    atomicAdd(&g_cnt[s * NTYPES + td],  1);
    atomicAdd(&g_cnt[d * NTYPES + ts], -1);
    atomicAdd(&g_deg[d], 1);
}

// ---------------------------------------------------------------- K2: normalize + transpose
// entity_reps is [D, n_nodes] row-major; tid = i*n_nodes + n gives coalesced reads.
__global__ void k_norm(const float* __restrict__ reps, int n_nodes) {
    int tid = blockIdx.x * blockDim.x + threadIdx.x;
    int total = D * n_nodes;
    if (tid >= total) return;
    int i = tid / n_nodes;
    int n = tid - i * n_nodes;
    int deg = g_deg[n];
    float inv = (deg > 0) ? rsqrtf((float)deg) : 0.0f;
    g_xT[n * D + i] = reps[tid] * inv;
}

// ---------------------------------------------------------------- K3: per-node weighted matvec + sum-of-squares
// comparison[v] = (sum_t cnt[v][t] * R[tv][t]) @ x[v]; out += ||comparison[v]||^2
// Block = 256 threads = 16 nodes x 16 rows.
__global__ void __launch_bounds__(256)
k_node(const float* __restrict__ R,       // [16,16,16,16]
       const int*   __restrict__ types,
       int n_nodes, float* out) {
    __shared__ float sx[16][D];     // x-vectors for this block's nodes
    __shared__ int   scnt[16][NTYPES];
    __shared__ int   stv[16];

    int local = threadIdx.x >> 4;   // node slot within block
    int i     = threadIdx.x & 15;   // output row
    int v     = blockIdx.x * 16 + local;

    if (v < n_nodes) {
        sx[local][i]   = g_xT[v * D + i];        // coalesced 64B per node
        scnt[local][i] = g_cnt[v * NTYPES + i];  // coalesced
        if (i == 0) stv[local] = types[v];
    }
    __syncthreads();

    float acc = 0.0f;
    if (v < n_nodes) {
        int tv = stv[local];
        const float4* Rb = reinterpret_cast<const float4*>(R) + (tv << 10); // R[tv]: 4096 floats = 1024 float4
        // x into registers (shared broadcast within node group)
        const float4* xs = reinterpret_cast<const float4*>(sx[local]);
        float4 x0 = xs[0], x1 = xs[1], x2 = xs[2], x3 = xs[3];

        float y = 0.0f;
        #pragma unroll
        for (int t = 0; t < NTYPES; t++) {
            int n = scnt[local][t];
            if (n == 0) continue;               // uniform per node group
            const float4* row = Rb + (t << 6) + (i << 2);   // R[tv][t][i][:]
            float4 r0 = row[0], r1 = row[1], r2 = row[2], r3 = row[3];
            float dotv = r0.x*x0.x + r0.y*x0.y + r0.z*x0.z + r0.w*x0.w
                       + r1.x*x1.x + r1.y*x1.y + r1.z*x1.z + r1.w*x1.w
                       + r2.x*x2.x + r2.y*x2.y + r2.z*x2.z + r2.w*x2.w
                       + r3.x*x3.x + r3.y*x3.y + r3.z*x3.z + r3.w*x3.w;
            y = fmaf((float)n, dotv, y);
        }
        acc = y * y;
    }

    // block reduce -> one atomicAdd per block
    #pragma unroll
    for (int off = 16; off > 0; off >>= 1)
        acc += __shfl_down_sync(0xFFFFFFFFu, acc, off);
    __shared__ float warp_sums[8];
    int lane = threadIdx.x & 31;
    int wid  = threadIdx.x >> 5;
    if (lane == 0) warp_sums[wid] = acc;
    __syncthreads();
    if (wid == 0) {
        float s = (lane < 8) ? warp_sums[lane] : 0.0f;
        #pragma unroll
        for (int off = 4; off > 0; off >>= 1)
            s += __shfl_down_sync(0xFFu, s, off);
        if (lane == 0) atomicAdd(out, s);
    }
}

// ---------------------------------------------------------------- launch
extern "C" void kernel_launch(void* const* d_in, const int* in_sizes, int n_in,
                              void* d_out, int out_size) {
    const float* reps  = (const float*)d_in[0];  // [16, n_nodes]
    const float* rmaps = (const float*)d_in[1];  // [16,16,16,16]
    const int*   eidx  = (const int*)d_in[2];    // [2, n_edges]
    const int*   types = (const int*)d_in[3];    // [n_nodes]
    float* out = (float*)d_out;

    int n_nodes = in_sizes[3];
    if (n_nodes > MAX_NODES) n_nodes = MAX_NODES;   // defensive: scratch bound
    int n_edges = in_sizes[2] / 2;
    const int* src = eidx;
    const int* dst = eidx + n_edges;

    const int T = 256;
    int total_nt = n_nodes * NTYPES;

    k_zero <<<(total_nt + T - 1) / T, T>>>(n_nodes, out);
    k_count<<<(n_edges + T - 1) / T, T>>>(src, dst, types, n_edges);
    k_norm <<<(n_nodes * D + T - 1) / T, T>>>(reps, n_nodes);
    k_node <<<(n_nodes + 15) / 16, 256>>>(rmaps, types, n_nodes, out);
}

// round 6
// speedup vs baseline: 5.8207x; 1.4073x over previous
#include <cuda_runtime.h>
#include <cuda_bf16.h>
#include <math.h>

#define MAX_NODES 50000
#define D 16
#define NTYPES 16

// Scratch (allocation-free rule: __device__ globals)
__device__ int   g_cnt[MAX_NODES * NTYPES]; // signed type counts per node
__device__ int   g_deg[MAX_NODES];          // in-degree (on dst)
__device__ float g_xT[MAX_NODES * D];       // node-major normalized reps [n][16]
__device__ int   g_hist[NTYPES];
__device__ int   g_off[NTYPES + 1];
__device__ int   g_pos[NTYPES];
__device__ int   g_sorted[MAX_NODES];

// ---------------------------------------------------------------- K0: zero scratch + out
__global__ void k_zero(int n_nodes, float* out) {
    int i = blockIdx.x * blockDim.x + threadIdx.x;
    int total = n_nodes * NTYPES;
    if (i < total) g_cnt[i] = 0;
    if (i < n_nodes) g_deg[i] = 0;
    if (i < NTYPES) { g_hist[i] = 0; g_pos[i] = 0; }
    if (i == 0) out[0] = 0.0f;
}

// ---------------------------------------------------------------- K1: per-edge type counts + degree (+ node-type histogram)
// head at src uses R[ts][td]  -> cnt[s][td] += 1
// tail at dst uses R[td][ts]  -> cnt[d][ts] -= 1
__global__ void __launch_bounds__(256)
k_count(const int* __restrict__ src, const int* __restrict__ dst,
        const int* __restrict__ types, int n_edges, int n_nodes) {
    int e = blockIdx.x * blockDim.x + threadIdx.x;
    if (e < n_edges) {
        int s  = src[e];
        int d  = dst[e];
        int ts = __ldg(types + s);
        int td = __ldg(types + d);
        atomicAdd(&g_cnt[s * NTYPES + td],  1);
        atomicAdd(&g_cnt[d * NTYPES + ts], -1);
        atomicAdd(&g_deg[d], 1);
    }
    if (e < n_nodes) atomicAdd(&g_hist[__ldg(types + e)], 1);
}

// ---------------------------------------------------------------- K2: 16-bin exclusive scan (tiny)
__global__ void k_scan() {
    if (threadIdx.x == 0) {
        int acc = 0;
        #pragma unroll
        for (int t = 0; t < NTYPES; t++) {
            g_off[t] = acc;
            g_pos[t] = acc;
            acc += g_hist[t];
        }
        g_off[NTYPES] = acc;
    }
}

// ---------------------------------------------------------------- K3: scatter into type buckets + normalize/transpose x
__global__ void __launch_bounds__(256)
k_scatter(const float* __restrict__ reps, const int* __restrict__ types, int n_nodes) {
    int v = blockIdx.x * blockDim.x + threadIdx.x;
    if (v >= n_nodes) return;
    int t = types[v];
    int p = atomicAdd(&g_pos[t], 1);
    g_sorted[p] = v;

    int deg = g_deg[v];
    float inv = (deg > 0) ? rsqrtf((float)deg) : 0.0f;
    float o[D];
    #pragma unroll
    for (int i = 0; i < D; i++)
        o[i] = reps[i * n_nodes + v] * inv;   // coalesced across lanes for each i
    float4* dst = reinterpret_cast<float4*>(g_xT + v * D);
    #pragma unroll
    for (int k = 0; k < 4; k++)
        dst[k] = reinterpret_cast<const float4*>(o)[k];
}

// ---------------------------------------------------------------- K4: per-node weighted matvec + sum of squares
// Block serves ONE type: R[tv] staged in smem; thread = one node; all matrix
// reads are warp-uniform smem broadcasts (no replay).
__global__ void __launch_bounds__(256)
k_node(const float* __restrict__ R, float* out) {
    int type  = blockIdx.y;
    int start = g_off[type];
    int end   = g_off[type + 1];
    int base  = start + blockIdx.x * 256;
    if (base >= end) return;

    __shared__ float sR[NTYPES * D * D];      // 16 KB: R[type][t][i][j]
    {
        const float4* Rg = reinterpret_cast<const float4*>(R) + (type << 10);
        float4* s4 = reinterpret_cast<float4*>(sR);
        #pragma unroll
        for (int k = 0; k < 4; k++)
            s4[threadIdx.x + k * 256] = Rg[threadIdx.x + k * 256];
    }
    __syncthreads();

    int idx = base + threadIdx.x;
    float acc = 0.0f;
    if (idx < end) {
        int v = g_sorted[idx];
        const float4* xg = reinterpret_cast<const float4*>(g_xT + v * D);
        float4 x0 = xg[0], x1 = xg[1], x2 = xg[2], x3 = xg[3];
        const int4* cg = reinterpret_cast<const int4*>(g_cnt + v * NTYPES);
        int4 c0 = cg[0], c1 = cg[1], c2 = cg[2], c3 = cg[3];
        float cf[NTYPES] = {
            (float)c0.x, (float)c0.y, (float)c0.z, (float)c0.w,
            (float)c1.x, (float)c1.y, (float)c1.z, (float)c1.w,
            (float)c2.x, (float)c2.y, (float)c2.z, (float)c2.w,
            (float)c3.x, (float)c3.y, (float)c3.z, (float)c3.w };

        for (int i = 0; i < D; i++) {         // outer loop NOT unrolled (I$)
            float y = 0.0f;
            #pragma unroll
            for (int t = 0; t < NTYPES; t++) {
                const float4* row = reinterpret_cast<const float4*>(sR + t * 256 + i * 16);
                float4 r0 = row[0], r1 = row[1], r2 = row[2], r3 = row[3];
                float dotv = r0.x*x0.x + r0.y*x0.y + r0.z*x0.z + r0.w*x0.w
                           + r1.x*x1.x + r1.y*x1.y + r1.z*x1.z + r1.w*x1.w
                           + r2.x*x2.x + r2.y*x2.y + r2.z*x2.z + r2.w*x2.w
                           + r3.x*x3.x + r3.y*x3.y + r3.z*x3.z + r3.w*x3.w;
                y = fmaf(cf[t], dotv, y);
            }
            acc = fmaf(y, y, acc);
        }
    }

    // block reduce -> one atomicAdd per block
    #pragma unroll
    for (int off = 16; off > 0; off >>= 1)
        acc += __shfl_down_sync(0xFFFFFFFFu, acc, off);
    __shared__ float warp_sums[8];
    int lane = threadIdx.x & 31;
    int wid  = threadIdx.x >> 5;
    if (lane == 0) warp_sums[wid] = acc;
    __syncthreads();
    if (wid == 0) {
        float s = (lane < 8) ? warp_sums[lane] : 0.0f;
        #pragma unroll
        for (int off = 4; off > 0; off >>= 1)
            s += __shfl_down_sync(0xFFu, s, off);
        if (lane == 0) atomicAdd(out, s);
    }
}

// ---------------------------------------------------------------- launch
extern "C" void kernel_launch(void* const* d_in, const int* in_sizes, int n_in,
                              void* d_out, int out_size) {
    const float* reps  = (const float*)d_in[0];  // [16, n_nodes]
    const float* rmaps = (const float*)d_in[1];  // [16,16,16,16]
    const int*   eidx  = (const int*)d_in[2];    // [2, n_edges]
    const int*   types = (const int*)d_in[3];    // [n_nodes]
    float* out = (float*)d_out;

    int n_nodes = in_sizes[3];
    if (n_nodes > MAX_NODES) n_nodes = MAX_NODES;   // defensive: scratch bound
    int n_edges = in_sizes[2] / 2;
    const int* src = eidx;
    const int* dst = eidx + n_edges;

    const int T = 256;

    k_zero   <<<(n_nodes * NTYPES + T - 1) / T, T>>>(n_nodes, out);
    k_count  <<<(n_edges + T - 1) / T, T>>>(src, dst, types, n_edges, n_nodes);
    k_scan   <<<1, 32>>>();
    k_scatter<<<(n_nodes + T - 1) / T, T>>>(reps, types, n_nodes);

    dim3 grid((n_nodes + 255) / 256, NTYPES);   // most blocks early-exit
    k_node   <<<grid, 256>>>(rmaps, out);
}

// round 7
// speedup vs baseline: 7.0333x; 1.2083x over previous
#include <cuda_runtime.h>
#include <cuda_bf16.h>
#include <math.h>

#define MAX_NODES 50000
#define D 16
#define NTYPES 16

// Scratch (allocation-free rule: __device__ globals)
__device__ int   g_cnt_out[MAX_NODES * NTYPES]; // out-edge type counts
__device__ int   g_cnt_in [MAX_NODES * NTYPES]; // in-edge type counts
__device__ float g_invdeg[MAX_NODES];
__device__ float g_xT[MAX_NODES * D];           // node-major normalized reps
__device__ int   g_pos[NTYPES];                 // bucket fill counters -> final counts
__device__ int   g_bucket[NTYPES * MAX_NODES];  // per-type node lists

// ---------------------------------------------------------------- K0: zero counters + out
__global__ void k_zero(float* out) {
    int i = blockIdx.x * blockDim.x + threadIdx.x;
    int total4 = (MAX_NODES * NTYPES) / 4;   // 200000 int4 per array
    if (i < total4) {
        reinterpret_cast<int4*>(g_cnt_out)[i] = make_int4(0, 0, 0, 0);
        reinterpret_cast<int4*>(g_cnt_in )[i] = make_int4(0, 0, 0, 0);
    }
    if (i < NTYPES) g_pos[i] = 0;
    if (i == 0) out[0] = 0.0f;
}

// ---------------------------------------------------------------- K1: per-edge type counts (2 atomics/edge)
// head at src uses R[ts][td]  -> cnt_out[s][td] += 1
// tail at dst uses R[td][ts]  -> cnt_in [d][ts] += 1   (in-degree = row sum)
__global__ void __launch_bounds__(256)
k_count(const int* __restrict__ src, const int* __restrict__ dst,
        const int* __restrict__ types, int n_edges) {
    int e = blockIdx.x * blockDim.x + threadIdx.x;
    if (e >= n_edges) return;
    int s  = src[e];
    int d  = dst[e];
    int ts = __ldg(types + s);
    int td = __ldg(types + d);
    atomicAdd(&g_cnt_out[s * NTYPES + td], 1);
    atomicAdd(&g_cnt_in [d * NTYPES + ts], 1);
}

// ---------------------------------------------------------------- K2: block-aggregated bucket scatter + invdeg
__global__ void __launch_bounds__(256)
k_scatter(const int* __restrict__ types, int n_nodes) {
    __shared__ int s_hist[NTYPES];
    __shared__ int s_base[NTYPES];
    int tid = threadIdx.x;
    int v   = blockIdx.x * 256 + tid;

    if (tid < NTYPES) s_hist[tid] = 0;
    __syncthreads();

    int t = 0, lrank = 0;
    if (v < n_nodes) {
        t = __ldg(types + v);
        lrank = atomicAdd(&s_hist[t], 1);   // smem atomic, low contention
    }
    __syncthreads();
    if (tid < NTYPES) s_base[tid] = atomicAdd(&g_pos[tid], s_hist[tid]);
    __syncthreads();

    if (v < n_nodes) {
        g_bucket[t * MAX_NODES + s_base[t] + lrank] = v;
        // in-degree = sum of cnt_in row
        const int4* ci = reinterpret_cast<const int4*>(g_cnt_in + v * NTYPES);
        int4 a = ci[0], b = ci[1], c = ci[2], e = ci[3];
        int deg = a.x+a.y+a.z+a.w + b.x+b.y+b.z+b.w + c.x+c.y+c.z+c.w + e.x+e.y+e.z+e.w;
        g_invdeg[v] = (deg > 0) ? rsqrtf((float)deg) : 0.0f;
    }
}

// ---------------------------------------------------------------- K3: normalize + transpose (element-per-thread)
__global__ void k_norm(const float* __restrict__ reps, int n_nodes) {
    int tid = blockIdx.x * blockDim.x + threadIdx.x;
    int total = D * n_nodes;
    if (tid >= total) return;
    int i = tid / n_nodes;
    int n = tid - i * n_nodes;
    g_xT[n * D + i] = reps[tid] * g_invdeg[n];   // coalesced read, scattered 4B write
}

// ---------------------------------------------------------------- K4: per-node weighted matvec + sum of squares
// Block serves ONE type: R[tv] staged in smem; thread = one node; all matrix
// reads are warp-uniform smem broadcasts.
__global__ void __launch_bounds__(256)
k_node(const float* __restrict__ R, float* out) {
    int type  = blockIdx.y;
    int count = g_pos[type];
    int base  = blockIdx.x * 256;
    if (base >= count) return;

    __shared__ float sR[NTYPES * D * D];      // 16 KB: R[type][t][i][j]
    {
        const float4* Rg = reinterpret_cast<const float4*>(R) + (type << 10);
        float4* s4 = reinterpret_cast<float4*>(sR);
        #pragma unroll
        for (int k = 0; k < 4; k++)
            s4[threadIdx.x + k * 256] = Rg[threadIdx.x + k * 256];
    }
    __syncthreads();

    int idx = base + threadIdx.x;
    float acc = 0.0f;
    if (idx < count) {
        int v = g_bucket[type * MAX_NODES + idx];
        const float4* xg = reinterpret_cast<const float4*>(g_xT + v * D);
        float4 x0 = xg[0], x1 = xg[1], x2 = xg[2], x3 = xg[3];
        const int4* co = reinterpret_cast<const int4*>(g_cnt_out + v * NTYPES);
        const int4* ci = reinterpret_cast<const int4*>(g_cnt_in  + v * NTYPES);
        int4 o0 = co[0], o1 = co[1], o2 = co[2], o3 = co[3];
        int4 i0 = ci[0], i1 = ci[1], i2 = ci[2], i3 = ci[3];
        float cf[NTYPES] = {
            (float)(o0.x-i0.x), (float)(o0.y-i0.y), (float)(o0.z-i0.z), (float)(o0.w-i0.w),
            (float)(o1.x-i1.x), (float)(o1.y-i1.y), (float)(o1.z-i1.z), (float)(o1.w-i1.w),
            (float)(o2.x-i2.x), (float)(o2.y-i2.y), (float)(o2.z-i2.z), (float)(o2.w-i2.w),
            (float)(o3.x-i3.x), (float)(o3.y-i3.y), (float)(o3.z-i3.z), (float)(o3.w-i3.w) };

        for (int i = 0; i < D; i++) {         // outer loop NOT unrolled (I$)
            float y = 0.0f;
            #pragma unroll
            for (int t = 0; t < NTYPES; t++) {
                const float4* row = reinterpret_cast<const float4*>(sR + t * 256 + i * 16);
                float4 r0 = row[0], r1 = row[1], r2 = row[2], r3 = row[3];
                float dotv = r0.x*x0.x + r0.y*x0.y + r0.z*x0.z + r0.w*x0.w
                           + r1.x*x1.x + r1.y*x1.y + r1.z*x1.z + r1.w*x1.w
                           + r2.x*x2.x + r2.y*x2.y + r2.z*x2.z + r2.w*x2.w
                           + r3.x*x3.x + r3.y*x3.y + r3.z*x3.z + r3.w*x3.w;
                y = fmaf(cf[t], dotv, y);
            }
            acc = fmaf(y, y, acc);
        }
    }

    // block reduce -> one atomicAdd per block
    #pragma unroll
    for (int off = 16; off > 0; off >>= 1)
        acc += __shfl_down_sync(0xFFFFFFFFu, acc, off);
    __shared__ float warp_sums[8];
    int lane = threadIdx.x & 31;
    int wid  = threadIdx.x >> 5;
    if (lane == 0) warp_sums[wid] = acc;
    __syncthreads();
    if (wid == 0) {
        float s = (lane < 8) ? warp_sums[lane] : 0.0f;
        #pragma unroll
        for (int off = 4; off > 0; off >>= 1)
            s += __shfl_down_sync(0xFFu, s, off);
        if (lane == 0) atomicAdd(out, s);
    }
}

// ---------------------------------------------------------------- launch
extern "C" void kernel_launch(void* const* d_in, const int* in_sizes, int n_in,
                              void* d_out, int out_size) {
    const float* reps  = (const float*)d_in[0];  // [16, n_nodes]
    const float* rmaps = (const float*)d_in[1];  // [16,16,16,16]
    const int*   eidx  = (const int*)d_in[2];    // [2, n_edges]
    const int*   types = (const int*)d_in[3];    // [n_nodes]
    float* out = (float*)d_out;

    int n_nodes = in_sizes[3];
    if (n_nodes > MAX_NODES) n_nodes = MAX_NODES;   // defensive: scratch bound
    int n_edges = in_sizes[2] / 2;
    const int* src = eidx;
    const int* dst = eidx + n_edges;

    const int T = 256;

    k_zero   <<<(MAX_NODES * NTYPES / 4 + T - 1) / T, T>>>(out);
    k_count  <<<(n_edges + T - 1) / T, T>>>(src, dst, types, n_edges);
    k_scatter<<<(n_nodes + T - 1) / T, T>>>(types, n_nodes);
    k_norm   <<<(n_nodes * D + T - 1) / T, T>>>(reps, n_nodes);

    dim3 grid((n_nodes + 255) / 256, NTYPES);   // most blocks early-exit
    k_node   <<<grid, 256>>>(rmaps, out);
}